// round 17
// baseline (speedup 1.0000x reference)
#include <cuda_runtime.h>
#include <cuda_fp16.h>

#define NNODES 100000
#define CDIM   128
#define EDGES  3200000

// prep kernel block partition
#define XBLK 6250     // NNODES*CDIM/8/256
#define WBLK 40       // 81920 weight halves /8/256
#define HBLK 1563     // ceil(EDGES/8/256)
#define ALLOC_BLK 391 // ceil(NNODES/256)

// Scratch (__device__ globals; no allocation allowed). fp16 feature plane.
__device__ __half g_xh  [(size_t)NNODES * CDIM];
__device__ __half g_aggh[(size_t)NNODES * CDIM];
__device__ __half g_h1h [(size_t)NNODES * CDIM];
__device__ __half g_th  [(size_t)NNODES * 64];    // proj cols 0..63 (fp16)
__device__ float  g_ts  [(size_t)NNODES * 64];    // proj cols 64..127 (fp32 self)
__device__ __half g_wh  [81920];                  // fp16 weights, concatenated
__device__ float  g_inv[NNODES];
__device__ int    g_deg[NNODES];
__device__ int    g_rowstart[NNODES];
__device__ int    g_wcur[NNODES];
__device__ int    g_eidx[EDGES];
__device__ int    g_cur[1];

// ---------------------------------------------------------------------------
__device__ __forceinline__ uint4 f8h8_(float4 f0, float4 f1) {
    __half2 h0 = __float22half2_rn(make_float2(f0.x, f0.y));
    __half2 h1 = __float22half2_rn(make_float2(f0.z, f0.w));
    __half2 h2 = __float22half2_rn(make_float2(f1.x, f1.y));
    __half2 h3 = __float22half2_rn(make_float2(f1.z, f1.w));
    uint4 v;
    v.x = *(unsigned*)&h0; v.y = *(unsigned*)&h1;
    v.z = *(unsigned*)&h2; v.w = *(unsigned*)&h3;
    return v;
}

// ---------------------------------------------------------------------------
// PREP (grid-partitioned): x->fp16, weights->fp16, degree hist, cursor=0
__global__ void prep_kernel(const float* __restrict__ x, __half* __restrict__ xh,
                            const float* __restrict__ Wl1, const float* __restrict__ Wr1,
                            const float* __restrict__ Wl2, const float* __restrict__ Wr2,
                            const float* __restrict__ Wl3, const float* __restrict__ Wr3,
                            __half* __restrict__ wh,
                            const int* __restrict__ ei, int* __restrict__ deg,
                            int* __restrict__ cursor) {
    int b = blockIdx.x;
    if (b < XBLK) {
        long long i = (long long)b * 256 + threadIdx.x;
        const float4* p = (const float4*)(x + i * 8);
        *(uint4*)(xh + i * 8) = f8h8_(p[0], p[1]);
    } else if (b < XBLK + WBLK) {
        if (b == XBLK && threadIdx.x == 0) *cursor = 0;
        int wi = (b - XBLK) * 256 + threadIdx.x;
        int off = wi * 8;
        const float* src;
        if      (off < 16384) src = Wl1 + off;
        else if (off < 32768) src = Wr1 + off - 16384;
        else if (off < 49152) src = Wl2 + off - 32768;
        else if (off < 65536) src = Wr2 + off - 49152;
        else if (off < 73728) src = Wl3 + off - 65536;
        else                  src = Wr3 + off - 73728;
        const float4* p = (const float4*)src;
        *(uint4*)(wh + off) = f8h8_(p[0], p[1]);
    } else {
        int e8 = ((b - XBLK - WBLK) * 256 + threadIdx.x) * 8;
        if (e8 + 7 < EDGES) {
            int4 d0 = *(const int4*)(ei + EDGES + e8);
            int4 d1 = *(const int4*)(ei + EDGES + e8 + 4);
            atomicAdd(deg + d0.x, 1); atomicAdd(deg + d0.y, 1);
            atomicAdd(deg + d0.z, 1); atomicAdd(deg + d0.w, 1);
            atomicAdd(deg + d1.x, 1); atomicAdd(deg + d1.y, 1);
            atomicAdd(deg + d1.z, 1); atomicAdd(deg + d1.w, 1);
        } else {
            for (int e = e8; e < EDGES; e++)
                atomicAdd(deg + ei[EDGES + e], 1);
        }
    }
}

// ---------------------------------------------------------------------------
// Segment allocation: warp-scan degrees, ONE cursor atomic per warp.
// Segments are contiguous per node; global placement order is arbitrary.
__global__ void alloc_kernel(const int* __restrict__ deg, int* __restrict__ cursor,
                             int* __restrict__ rowstart, int* __restrict__ wcur,
                             float* __restrict__ inv) {
    int i = blockIdx.x * blockDim.x + threadIdx.x;
    int lane = threadIdx.x & 31;
    int v = (i < NNODES) ? deg[i] : 0;
    int x = v;
#pragma unroll
    for (int off = 1; off < 32; off <<= 1) {
        int y = __shfl_up_sync(0xffffffffu, x, off);
        if (lane >= off) x += y;
    }
    int base = 0;
    if (lane == 31) base = atomicAdd(cursor, x);     // x = warp total (inclusive)
    base = __shfl_sync(0xffffffffu, base, 31);
    if (i < NNODES) {
        int st = base + x - v;                        // exclusive within warp
        rowstart[i] = st;
        wcur[i]     = st;
        inv[i]      = 1.0f / fmaxf((float)v, 1.0f);
    }
}

// fill CSR adjacency, 8 edges per thread (ILP)
__global__ void fill_kernel(const int* __restrict__ ei, int* __restrict__ wcur,
                            int* __restrict__ eidx) {
    int e8 = (blockIdx.x * blockDim.x + threadIdx.x) * 8;
    if (e8 + 7 < EDGES) {
        int4 s0 = *(const int4*)(ei + e8);
        int4 s1 = *(const int4*)(ei + e8 + 4);
        int4 d0 = *(const int4*)(ei + EDGES + e8);
        int4 d1 = *(const int4*)(ei + EDGES + e8 + 4);
        int p0 = atomicAdd(wcur + d0.x, 1);
        int p1 = atomicAdd(wcur + d0.y, 1);
        int p2 = atomicAdd(wcur + d0.z, 1);
        int p3 = atomicAdd(wcur + d0.w, 1);
        int p4 = atomicAdd(wcur + d1.x, 1);
        int p5 = atomicAdd(wcur + d1.y, 1);
        int p6 = atomicAdd(wcur + d1.z, 1);
        int p7 = atomicAdd(wcur + d1.w, 1);
        eidx[p0] = s0.x; eidx[p1] = s0.y; eidx[p2] = s0.z; eidx[p3] = s0.w;
        eidx[p4] = s1.x; eidx[p5] = s1.y; eidx[p6] = s1.z; eidx[p7] = s1.w;
    } else {
        for (int e = e8; e < EDGES; e++) {
            int pos = atomicAdd(wcur + ei[EDGES + e], 1);
            eidx[pos] = ei[e];
        }
    }
}

// ---------------------------------------------------------------------------
// Gather-aggregate (fp16 in, fp32 accumulate, fp16 mean out): warp per node.
__global__ void aggregate128_kernel(const int* __restrict__ rowstart,
                                    const int* __restrict__ deg,
                                    const int* __restrict__ eidx,
                                    const __half* __restrict__ hh,
                                    const float* __restrict__ inv,
                                    __half* __restrict__ out) {
    int warp = (blockIdx.x * blockDim.x + threadIdx.x) >> 5;
    int lane = threadIdx.x & 31;
    if (warp >= NNODES) return;
    int s = rowstart[warp];
    int e = s + deg[warp];

    float acc[4] = {0.f, 0.f, 0.f, 0.f};

    int i = s;
    for (; i + 3 < e; i += 4) {
        int s0 = eidx[i], s1 = eidx[i+1], s2 = eidx[i+2], s3 = eidx[i+3];
        uint2 u0 = *(const uint2*)(hh + (size_t)s0 * 128 + lane * 4);
        uint2 u1 = *(const uint2*)(hh + (size_t)s1 * 128 + lane * 4);
        uint2 u2 = *(const uint2*)(hh + (size_t)s2 * 128 + lane * 4);
        uint2 u3 = *(const uint2*)(hh + (size_t)s3 * 128 + lane * 4);
        float2 a, b;
        a = __half22float2(*(__half2*)&u0.x); acc[0] += a.x; acc[1] += a.y;
        b = __half22float2(*(__half2*)&u0.y); acc[2] += b.x; acc[3] += b.y;
        a = __half22float2(*(__half2*)&u1.x); acc[0] += a.x; acc[1] += a.y;
        b = __half22float2(*(__half2*)&u1.y); acc[2] += b.x; acc[3] += b.y;
        a = __half22float2(*(__half2*)&u2.x); acc[0] += a.x; acc[1] += a.y;
        b = __half22float2(*(__half2*)&u2.y); acc[2] += b.x; acc[3] += b.y;
        a = __half22float2(*(__half2*)&u3.x); acc[0] += a.x; acc[1] += a.y;
        b = __half22float2(*(__half2*)&u3.y); acc[2] += b.x; acc[3] += b.y;
    }
    for (; i < e; i++) {
        uint2 u0 = *(const uint2*)(hh + (size_t)eidx[i] * 128 + lane * 4);
        float2 a = __half22float2(*(__half2*)&u0.x);
        float2 b = __half22float2(*(__half2*)&u0.y);
        acc[0] += a.x; acc[1] += a.y; acc[2] += b.x; acc[3] += b.y;
    }

    float iv = inv[warp];
    __half2 p0 = __float22half2_rn(make_float2(acc[0]*iv, acc[1]*iv));
    __half2 p1 = __float22half2_rn(make_float2(acc[2]*iv, acc[3]*iv));
    uint2 st;
    st.x = *(unsigned*)&p0; st.y = *(unsigned*)&p1;
    *(uint2*)(out + (size_t)warp * 128 + lane * 4) = st;
}

// Layer-3 fused aggregate: mean(th 64-wide) + ts[n,c] + bl3[c] -> out (fp32)
__global__ void aggregate_final_kernel(const int* __restrict__ rowstart,
                                       const int* __restrict__ deg,
                                       const int* __restrict__ eidx,
                                       const __half* __restrict__ th,
                                       const float* __restrict__ ts,
                                       const float* __restrict__ bl,
                                       const float* __restrict__ inv,
                                       float* __restrict__ out) {
    int warp = (blockIdx.x * blockDim.x + threadIdx.x) >> 5;
    int lane = threadIdx.x & 31;
    if (warp >= NNODES) return;
    int s = rowstart[warp];
    int e = s + deg[warp];

    float a0 = 0.f, a1 = 0.f;
    int i = s;
    for (; i + 3 < e; i += 4) {
        int s0 = eidx[i], s1 = eidx[i+1], s2 = eidx[i+2], s3 = eidx[i+3];
        unsigned u0 = *(const unsigned*)(th + (size_t)s0 * 64 + lane * 2);
        unsigned u1 = *(const unsigned*)(th + (size_t)s1 * 64 + lane * 2);
        unsigned u2 = *(const unsigned*)(th + (size_t)s2 * 64 + lane * 2);
        unsigned u3 = *(const unsigned*)(th + (size_t)s3 * 64 + lane * 2);
        float2 a;
        a = __half22float2(*(__half2*)&u0); a0 += a.x; a1 += a.y;
        a = __half22float2(*(__half2*)&u1); a0 += a.x; a1 += a.y;
        a = __half22float2(*(__half2*)&u2); a0 += a.x; a1 += a.y;
        a = __half22float2(*(__half2*)&u3); a0 += a.x; a1 += a.y;
    }
    for (; i < e; i++) {
        unsigned u0 = *(const unsigned*)(th + (size_t)eidx[i] * 64 + lane * 2);
        float2 a = __half22float2(*(__half2*)&u0);
        a0 += a.x; a1 += a.y;
    }

    float iv = inv[warp];
    float2 self = *(const float2*)(ts + (size_t)warp * 64 + lane * 2);
    float2 bb   = *(const float2*)(bl + lane * 2);
    *(float2*)(out + (size_t)warp * 64 + lane * 2) =
        make_float2(a0 * iv + self.x + bb.x, a1 * iv + self.y + bb.y);
}

// ---------------------------------------------------------------------------
#define MMA_16816(c, a, b) \
    asm volatile("mma.sync.aligned.m16n8k16.row.col.f32.f16.f16.f32 " \
        "{%0,%1,%2,%3}, {%4,%5,%6,%7}, {%8,%9}, {%0,%1,%2,%3};" \
        : "+f"((c)[0]), "+f"((c)[1]), "+f"((c)[2]), "+f"((c)[3]) \
        : "r"((a)[0]), "r"((a)[1]), "r"((a)[2]), "r"((a)[3]), \
          "r"((b)[0]), "r"((b)[1]))

// combine (layer 1): outh[n,c] = relu( mean@Wl^T + bl + h@Wr^T ) -> fp16
__global__ __launch_bounds__(256)
void combine_tc(const __half* __restrict__ mean, const __half* __restrict__ h,
                const __half* __restrict__ Wl, const float* __restrict__ bl,
                const __half* __restrict__ Wr, __half* __restrict__ outh) {
    constexpr int BM = 128, BN = 128, BK = 64, LD = 72;
    __shared__ __half As[BM][LD];
    __shared__ __half Bs[BN][LD];

    const int tid = threadIdx.x, wid = tid >> 5, lane = tid & 31;
    const int m0 = blockIdx.x * BM;
    const int wm = (wid & 3) * 32;
    const int wn = (wid >> 2) * 64;

    float acc[2][8][4];
#pragma unroll
    for (int i = 0; i < 2; i++)
#pragma unroll
        for (int j = 0; j < 8; j++)
#pragma unroll
            for (int d = 0; d < 4; d++) acc[i][j][d] = 0.f;

#pragma unroll
    for (int phase = 0; phase < 2; phase++) {
        const __half* A = phase ? h  : mean;
        const __half* B = phase ? Wr : Wl;
#pragma unroll
        for (int kc = 0; kc < CDIM; kc += BK) {
            __syncthreads();
#pragma unroll
            for (int s = tid; s < BM * BK / 8; s += 256) {
                int m = s >> 3, kg = (s & 7) * 8;
                uint4 v = make_uint4(0, 0, 0, 0);
                int node = m0 + m;
                if (node < NNODES)
                    v = *(const uint4*)(A + (size_t)node * CDIM + kc + kg);
                *(uint4*)&As[m][kg] = v;
            }
#pragma unroll
            for (int s = tid; s < BN * BK / 8; s += 256) {
                int c = s >> 3, kg = (s & 7) * 8;
                *(uint4*)&Bs[c][kg] = *(const uint4*)(B + (size_t)c * CDIM + kc + kg);
            }
            __syncthreads();

#pragma unroll
            for (int ks = 0; ks < 4; ks++) {
                int k0 = ks * 16;
                unsigned a[2][4];
#pragma unroll
                for (int mf = 0; mf < 2; mf++) {
                    int row = wm + mf * 16 + (lane & 15);
                    int col = k0 + ((lane >> 4) << 3);
                    unsigned addr = (unsigned)__cvta_generic_to_shared(&As[row][col]);
                    asm volatile("ldmatrix.sync.aligned.m8n8.x4.shared.b16 {%0,%1,%2,%3}, [%4];"
                        : "=r"(a[mf][0]), "=r"(a[mf][1]), "=r"(a[mf][2]), "=r"(a[mf][3])
                        : "r"(addr));
                }
#pragma unroll
                for (int nf = 0; nf < 8; nf++) {
                    int l = lane & 15;
                    int rown = wn + nf * 8 + (l & 7);
                    int col = k0 + ((l >> 3) << 3);
                    unsigned addr = (unsigned)__cvta_generic_to_shared(&Bs[rown][col]);
                    unsigned b[2];
                    asm volatile("ldmatrix.sync.aligned.m8n8.x2.shared.b16 {%0,%1}, [%2];"
                        : "=r"(b[0]), "=r"(b[1]) : "r"(addr));
                    MMA_16816(acc[0][nf], a[0], b);
                    MMA_16816(acc[1][nf], a[1], b);
                }
            }
        }
    }

    const int tg = lane >> 2;
    const int tc = (lane & 3) * 2;
#pragma unroll
    for (int mf = 0; mf < 2; mf++) {
#pragma unroll
        for (int nf = 0; nf < 8; nf++) {
            int n_ = wn + nf * 8 + tc;
            float b0 = bl[n_], b1 = bl[n_ + 1];
            int mA = m0 + wm + mf * 16 + tg;
            int mB = mA + 8;
            if (mA < NNODES) {
                __half2 hv = __float22half2_rn(make_float2(
                    fmaxf(acc[mf][nf][0] + b0, 0.f), fmaxf(acc[mf][nf][1] + b1, 0.f)));
                *(__half2*)(outh + (size_t)mA * BN + n_) = hv;
            }
            if (mB < NNODES) {
                __half2 hv = __float22half2_rn(make_float2(
                    fmaxf(acc[mf][nf][2] + b0, 0.f), fmaxf(acc[mf][nf][3] + b1, 0.f)));
                *(__half2*)(outh + (size_t)mB * BN + n_) = hv;
            }
        }
    }
}

// ---------------------------------------------------------------------------
// FUSED layer-2 combine + layer-3 proj (h2 tile stays in smem)
#define TILE_LD 136
#define FUSE_SMEM ((128 * TILE_LD + 128 * 72) * 2)

__global__ __launch_bounds__(256)
void combine_proj_tc(const __half* __restrict__ mean, const __half* __restrict__ h,
                     const __half* __restrict__ Wl2, const float* __restrict__ bl2,
                     const __half* __restrict__ Wr2,
                     const __half* __restrict__ Wl3, const __half* __restrict__ Wr3,
                     __half* __restrict__ th, float* __restrict__ ts) {
    extern __shared__ __half sm[];
    __half (*tile)[TILE_LD] = (__half(*)[TILE_LD])sm;
    __half (*Bs)[72]        = (__half(*)[72])(sm + 128 * TILE_LD);

    const int tid = threadIdx.x, wid = tid >> 5, lane = tid & 31;
    const int m0 = blockIdx.x * 128;
    const int wm = (wid & 3) * 32;
    const int wn = (wid >> 2) * 64;
    const int tg = lane >> 2;
    const int tc = (lane & 3) * 2;

    float acc[2][8][4];
#pragma unroll
    for (int i = 0; i < 2; i++)
#pragma unroll
        for (int j = 0; j < 8; j++)
#pragma unroll
            for (int d = 0; d < 4; d++) acc[i][j][d] = 0.f;

    // ---- stage 1: layer-2 combine ----
#pragma unroll
    for (int phase = 0; phase < 2; phase++) {
        const __half* A = phase ? h   : mean;
        const __half* B = phase ? Wr2 : Wl2;
#pragma unroll
        for (int kc = 0; kc < CDIM; kc += 64) {
            __syncthreads();
#pragma unroll
            for (int s = tid; s < 128 * 8; s += 256) {
                int m = s >> 3, kg = (s & 7) * 8;
                uint4 v = make_uint4(0, 0, 0, 0);
                int node = m0 + m;
                if (node < NNODES)
                    v = *(const uint4*)(A + (size_t)node * CDIM + kc + kg);
                *(uint4*)&tile[m][kg] = v;
            }
#pragma unroll
            for (int s = tid; s < 128 * 8; s += 256) {
                int c = s >> 3, kg = (s & 7) * 8;
                *(uint4*)&Bs[c][kg] = *(const uint4*)(B + (size_t)c * CDIM + kc + kg);
            }
            __syncthreads();
#pragma unroll
            for (int ks = 0; ks < 4; ks++) {
                int k0 = ks * 16;
                unsigned a[2][4];
#pragma unroll
                for (int mf = 0; mf < 2; mf++) {
                    int row = wm + mf * 16 + (lane & 15);
                    int col = k0 + ((lane >> 4) << 3);
                    unsigned addr = (unsigned)__cvta_generic_to_shared(&tile[row][col]);
                    asm volatile("ldmatrix.sync.aligned.m8n8.x4.shared.b16 {%0,%1,%2,%3}, [%4];"
                        : "=r"(a[mf][0]), "=r"(a[mf][1]), "=r"(a[mf][2]), "=r"(a[mf][3])
                        : "r"(addr));
                }
#pragma unroll
                for (int nf = 0; nf < 8; nf++) {
                    int l = lane & 15;
                    int rown = wn + nf * 8 + (l & 7);
                    int col = k0 + ((l >> 3) << 3);
                    unsigned addr = (unsigned)__cvta_generic_to_shared(&Bs[rown][col]);
                    unsigned b[2];
                    asm volatile("ldmatrix.sync.aligned.m8n8.x2.shared.b16 {%0,%1}, [%2];"
                        : "=r"(b[0]), "=r"(b[1]) : "r"(addr));
                    MMA_16816(acc[0][nf], a[0], b);
                    MMA_16816(acc[1][nf], a[1], b);
                }
            }
        }
    }

    // ---- epilogue 1: h2 -> fp16 into tile ----
    __syncthreads();
#pragma unroll
    for (int mf = 0; mf < 2; mf++) {
#pragma unroll
        for (int nf = 0; nf < 8; nf++) {
            int n_ = wn + nf * 8 + tc;
            float b0 = bl2[n_], b1 = bl2[n_ + 1];
            int rA = wm + mf * 16 + tg;
            __half2 hv0 = __float22half2_rn(make_float2(
                fmaxf(acc[mf][nf][0] + b0, 0.f), fmaxf(acc[mf][nf][1] + b1, 0.f)));
            __half2 hv1 = __float22half2_rn(make_float2(
                fmaxf(acc[mf][nf][2] + b0, 0.f), fmaxf(acc[mf][nf][3] + b1, 0.f)));
            *(__half2*)&tile[rA][n_]     = hv0;
            *(__half2*)&tile[rA + 8][n_] = hv1;
        }
    }
    __syncthreads();

    // ---- stage 2: proj GEMM over h2 tile (K = 128) ----
#pragma unroll
    for (int i = 0; i < 2; i++)
#pragma unroll
        for (int j = 0; j < 8; j++)
#pragma unroll
            for (int d = 0; d < 4; d++) acc[i][j][d] = 0.f;

#pragma unroll
    for (int kc = 0; kc < CDIM; kc += 64) {
        if (kc > 0) __syncthreads();
#pragma unroll
        for (int s = tid; s < 128 * 8; s += 256) {
            int c = s >> 3, kg = (s & 7) * 8;
            const __half* w = (c < 64) ? (Wl3 + (size_t)c * CDIM)
                                       : (Wr3 + (size_t)(c - 64) * CDIM);
            *(uint4*)&Bs[c][kg] = *(const uint4*)(w + kc + kg);
        }
        __syncthreads();
#pragma unroll
        for (int ks = 0; ks < 4; ks++) {
            int k0 = ks * 16;
            unsigned a[2][4];
#pragma unroll
            for (int mf = 0; mf < 2; mf++) {
                int row = wm + mf * 16 + (lane & 15);
                int col = kc + k0 + ((lane >> 4) << 3);
                unsigned addr = (unsigned)__cvta_generic_to_shared(&tile[row][col]);
                asm volatile("ldmatrix.sync.aligned.m8n8.x4.shared.b16 {%0,%1,%2,%3}, [%4];"
                    : "=r"(a[mf][0]), "=r"(a[mf][1]), "=r"(a[mf][2]), "=r"(a[mf][3])
                    : "r"(addr));
            }
#pragma unroll
            for (int nf = 0; nf < 8; nf++) {
                int l = lane & 15;
                int rown = wn + nf * 8 + (l & 7);
                int col = k0 + ((l >> 3) << 3);
                unsigned addr = (unsigned)__cvta_generic_to_shared(&Bs[rown][col]);
                unsigned b[2];
                asm volatile("ldmatrix.sync.aligned.m8n8.x2.shared.b16 {%0,%1}, [%2];"
                    : "=r"(b[0]), "=r"(b[1]) : "r"(addr));
                MMA_16816(acc[0][nf], a[0], b);
                MMA_16816(acc[1][nf], a[1], b);
            }
        }
    }

    // ---- epilogue 2: th (fp16) / ts (fp32) ----
#pragma unroll
    for (int mf = 0; mf < 2; mf++) {
#pragma unroll
        for (int nf = 0; nf < 8; nf++) {
            int n_ = wn + nf * 8 + tc;
            int mA = m0 + wm + mf * 16 + tg;
            int mB = mA + 8;
            if (n_ < 64) {
                if (mA < NNODES)
                    *(__half2*)(th + (size_t)mA * 64 + n_) = __float22half2_rn(
                        make_float2(acc[mf][nf][0], acc[mf][nf][1]));
                if (mB < NNODES)
                    *(__half2*)(th + (size_t)mB * 64 + n_) = __float22half2_rn(
                        make_float2(acc[mf][nf][2], acc[mf][nf][3]));
            } else {
                int c = n_ - 64;
                if (mA < NNODES)
                    *(float2*)(ts + (size_t)mA * 64 + c) =
                        make_float2(acc[mf][nf][0], acc[mf][nf][1]);
                if (mB < NNODES)
                    *(float2*)(ts + (size_t)mB * 64 + c) =
                        make_float2(acc[mf][nf][2], acc[mf][nf][3]);
            }
        }
    }
}

// ---------------------------------------------------------------------------
extern "C" void kernel_launch(void* const* d_in, const int* in_sizes, int n_in,
                              void* d_out, int out_size) {
    const float* x   = (const float*)d_in[0];
    const int*   ei  = (const int*)d_in[1];      // int32 (JAX x64 disabled)
    const float* Wl1 = (const float*)d_in[2];
    const float* bl1 = (const float*)d_in[3];
    const float* Wr1 = (const float*)d_in[4];
    const float* Wl2 = (const float*)d_in[5];
    const float* bl2 = (const float*)d_in[6];
    const float* Wr2 = (const float*)d_in[7];
    const float* Wl3 = (const float*)d_in[8];
    const float* bl3 = (const float*)d_in[9];
    const float* Wr3 = (const float*)d_in[10];
    float* out = (float*)d_out;

    __half *xh, *aggh, *h1h, *th, *wh;
    float *ts, *inv;
    int *deg, *rowstart, *wcur, *eidx, *cur;
    cudaGetSymbolAddress((void**)&xh,   g_xh);
    cudaGetSymbolAddress((void**)&aggh, g_aggh);
    cudaGetSymbolAddress((void**)&h1h,  g_h1h);
    cudaGetSymbolAddress((void**)&th,   g_th);
    cudaGetSymbolAddress((void**)&ts,   g_ts);
    cudaGetSymbolAddress((void**)&wh,   g_wh);
    cudaGetSymbolAddress((void**)&inv,  g_inv);
    cudaGetSymbolAddress((void**)&deg,  g_deg);
    cudaGetSymbolAddress((void**)&rowstart, g_rowstart);
    cudaGetSymbolAddress((void**)&wcur, g_wcur);
    cudaGetSymbolAddress((void**)&eidx, g_eidx);
    cudaGetSymbolAddress((void**)&cur,  g_cur);

    const __half* Wl1h = wh;
    const __half* Wr1h = wh + 16384;
    const __half* Wl2h = wh + 32768;
    const __half* Wr2h = wh + 49152;
    const __half* Wl3h = wh + 65536;
    const __half* Wr3h = wh + 73728;

    cudaFuncSetAttribute(combine_proj_tc,
                         cudaFuncAttributeMaxDynamicSharedMemorySize, FUSE_SMEM);

    const int e8Blocks = (EDGES / 8 + 255) / 256;
    const int aggBlocks = (NNODES * 32 + 255) / 256;   // warp per node
    const int combBlocks = (NNODES + 127) / 128;

    // --- prep (x->fp16 | weights->fp16 | hist | cursor=0) + CSR build ---
    cudaMemsetAsync(deg, 0, NNODES * sizeof(int), 0);
    prep_kernel<<<XBLK + WBLK + HBLK, 256>>>(x, xh, Wl1, Wr1, Wl2, Wr2, Wl3, Wr3,
                                             wh, ei, deg, cur);
    alloc_kernel<<<ALLOC_BLK, 256>>>(deg, cur, rowstart, wcur, inv);
    fill_kernel<<<e8Blocks, 256>>>(ei, wcur, eidx);

    // --- Layer 1: x -> h1h (relu) ---
    aggregate128_kernel<<<aggBlocks, 256>>>(rowstart, deg, eidx, xh, inv, aggh);
    combine_tc<<<combBlocks, 256>>>(aggh, xh, Wl1h, bl1, Wr1h, h1h);

    // --- Layer 2+3 GEMMs fused: h1h -> (th, ts) ---
    aggregate128_kernel<<<aggBlocks, 256>>>(rowstart, deg, eidx, h1h, inv, aggh);
    combine_proj_tc<<<combBlocks, 256, FUSE_SMEM>>>(aggh, h1h, Wl2h, bl2, Wr2h,
                                                    Wl3h, Wr3h, th, ts);

    // --- Layer 3 aggregate: mean(th) + ts + bl3 -> out ---
    aggregate_final_kernel<<<aggBlocks, 256>>>(rowstart, deg, eidx, th, ts, bl3,
                                               inv, out);
}